// round 12
// baseline (speedup 1.0000x reference)
#include <cuda_runtime.h>
#include <stdint.h>
#include <math.h>

#define NKPT 21
#define NANCH 12
#define BMAX 32
#define MAXA (12*128*128)
#define BSPLIT 4
#define CTILE 64
#define CTHREADS 512

__constant__ float c_ref[NKPT*2] = {
 213.33335876464844f, 124.50563049316406f,
 190.504638671875f,   115.11840057373047f,
 169.9791717529297f,  101.77180480957031f,
 146.72341918945312f,  96.25749206542969f,
 128.86770629882812f,  87.2344970703125f,
 150.34292602539062f, 101.61070251464844f,
 119.29926300048828f,  98.73982238769531f,
 100.03463745117188f,  99.74459838867188f,
  82.62400817871094f, 101.2509536743164f,
 148.91049194335938f, 112.71517181396484f,
 114.37303161621094f, 113.20121002197266f,
  91.90096282958984f, 116.49812316894531f,
  74.75020599365234f, 119.37875366210938f,
 149.59658813476562f, 124.09295654296875f,
 119.72419738769531f, 126.36898040771484f,
  99.59107208251953f, 129.40196228027344f,
  82.82524108886719f, 131.584228515625f,
 154.55911254882812f, 135.07681274414062f,
 133.8833770751953f,  140.85983276367188f,
 120.45906066894531f, 145.40306091308594f,
 106.21541595458984f, 150.072265625f
};

// (float)cos/sin of 0,90,180,270 deg (double-computed, cast)
__constant__ float c_trig[8] = {
 1.0f, 0.0f,
 6.123233995736766e-17f, 1.0f,
 -1.0f, 1.2246467991473532e-16f,
 -1.8369701987210297e-16f, -1.0f
};

// Per-(b,a) decision: 0=neg(inside), 1=left, 2=right, 3=outside.
__device__ uint8_t g_dec[(size_t)BMAX * MAXA];

__device__ __forceinline__ float ex2f(float x) {
    float y; asm("ex2.approx.f32 %0, %1;" : "=f"(y) : "f"(x)); return y;
}

__device__ __forceinline__ void ref_center(float& cx, float& cy) {
    float sx = 0.f, sy = 0.f;
    #pragma unroll
    for (int k = 0; k < NKPT; k++) { sx += c_ref[2*k]; sy += c_ref[2*k+1]; }
    cx = sx / 21.0f; cy = sy / 21.0f;
}

// base pose coordinate (no shift): bx/by = cx + sc*(rot) — float ops only
__device__ __forceinline__ float base_coord(int j, int k, int is_y,
                                            float cx, float cy) {
    int si = j >> 2, oi = j & 3;
    float sc  = (si == 0) ? 0.25f : ((si == 1) ? 0.5f : 1.0f);
    float cth = c_trig[2*oi], sth = c_trig[2*oi+1];
    float vx = c_ref[2*k]   - cx;
    float vy = c_ref[2*k+1] - cy;
    return is_y ? (cy + sc * (vx*sth + vy*cth))
                : (cx + sc * (vx*cth - vy*sth));
}

// -----------------------------------------------------------------------------
// Phase A: PURE decision kernel. 128 anchors/block, blockIdx.y = 4 batches.
// -----------------------------------------------------------------------------
__global__ void __launch_bounds__(128) phaseA_kernel(
    const float* __restrict__ gt,   // [B,2,21,3]
    const int*   __restrict__ ht,   // [B,2]
    const int*   __restrict__ fhp,
    const int*   __restrict__ fwp,
    int B, int A)
{
    __shared__ float s_gxy[BSPLIT*2*42];   // poisoned xy
    __shared__ float s_nc[BSPLIT*2];
    __shared__ float s_nvinv[BSPLIT*2];
    __shared__ int   s_ht[BSPLIT*2];

    const int tid = threadIdx.x;
    const int by  = blockIdx.y;
    const int bbase  = by * BSPLIT;
    const int bcount = min(BSPLIT, B - bbase);

    int feat_w, feat_h;
    if (fwp) { feat_w = *fwp; feat_h = *fhp; }
    else {
        int pos = A / NANCH;
        feat_w = (int)rintf(sqrtf((float)pos));
        feat_h = pos / feat_w;
    }

    const int ng = bcount * 84;
    for (int i = tid; i < ng; i += 128) {
        int b2 = i / 42, e = i - b2*42;
        int k = e >> 1;
        const float* base = gt + (size_t)(bbase*2 + b2)*63 + 3*k;
        float v   = base[e & 1];
        float vis = base[2];
        s_gxy[i] = (vis > 0.f) ? v : 1e19f;
    }
    if (tid < bcount*2) s_ht[tid] = ht[bbase*2 + tid];
    __syncthreads();

    if (tid < bcount*2) {
        const float* g = gt + (size_t)(bbase*2 + tid)*63;
        float xmn = 3.4e38f, xmx = -3.4e38f, ymn = 3.4e38f, ymx = -3.4e38f, nv = 0.f;
        #pragma unroll
        for (int k = 0; k < NKPT; k++) {
            float x = g[3*k], y = g[3*k+1];
            xmn = fminf(xmn, x); xmx = fmaxf(xmx, x);
            ymn = fminf(ymn, y); ymx = fmaxf(ymx, y);
            if (g[3*k+2] > 0.f) nv += 1.f;
        }
        float s2 = fmaxf((xmx - xmn) * (ymx - ymn), 1.f);
        s_nc[tid]    = -1.442695040888963f / (2.f * s2 * 0.01f);
        s_nvinv[tid] = 1.f / fmaxf(nv, 1.f);
    }
    __syncthreads();

    const int a = blockIdx.x * 128 + tid;
    if (a >= A) return;

    float cx, cy;
    ref_center(cx, cy);

    int j   = a % NANCH;
    int pos = a / NANCH;
    int ix  = pos % feat_w;
    int iy  = pos / feat_w;
    float shx = (float)((double)ix * (256.0 / (double)feat_w));
    float shy = (float)((double)iy * (256.0 / (double)feat_h));

    float ax[NKPT], ay[NKPT];
    bool inside = true;
    #pragma unroll
    for (int k = 0; k < NKPT; k++) {
        float px = base_coord(j, k, 0, cx, cy) + shx;
        float py = base_coord(j, k, 1, cx, cy) + shy;
        ax[k] = px; ay[k] = py;
        inside = inside && (px >= 0.f) && (py >= 0.f) && (px < 256.f) && (py < 256.f);
    }

    if (!inside) {
        for (int bl = 0; bl < bcount; bl++)
            g_dec[(size_t)(bbase + bl)*A + a] = 3;
    } else {
        for (int bl = 0; bl < bcount; bl++) {
            const float2* g0 = (const float2*)(s_gxy + bl*84);
            const float2* g1 = g0 + NKPT;
            float nc0 = s_nc[2*bl], nc1 = s_nc[2*bl+1];
            float acc0 = 0.f, acc1 = 0.f;
            #pragma unroll
            for (int k = 0; k < NKPT; k++) {
                float2 p0 = g0[k];
                float dx0 = ax[k] - p0.x, dy0 = ay[k] - p0.y;
                acc0 += ex2f((dx0*dx0 + dy0*dy0) * nc0);
                float2 p1 = g1[k];
                float dx1 = ax[k] - p1.x, dy1 = ay[k] - p1.y;
                acc1 += ex2f((dx1*dx1 + dy1*dy1) * nc1);
            }
            float sim0 = acc0 * s_nvinv[2*bl];
            float sim1 = acc1 * s_nvinv[2*bl+1];
            bool am0 = (sim0 >= sim1);
            float mxs = fmaxf(sim0, sim1);
            bool right = am0  && (mxs > 0.5f) && (s_ht[2*bl]   == 1);
            bool left  = !am0 && (mxs > 0.5f) && (s_ht[2*bl+1] == 1);
            g_dec[(size_t)(bbase + bl)*A + a] = right ? 2 : (left ? 1 : 0);
        }
    }
}

// -----------------------------------------------------------------------------
// Phase C: anchor tile assembled from base-pose table + per-pos shifts
// (doubles only for <=7 shift pairs). Writes anchors/inside/labels/offsets.
// -----------------------------------------------------------------------------
__global__ void __launch_bounds__(CTHREADS) phaseC_kernel(
    const float* __restrict__ gt,       // [B,2,21,3]
    const int*   __restrict__ fhp,
    const int*   __restrict__ fwp,
    float* __restrict__ anchors_out,    // [A,21,2]
    float* __restrict__ inside_out,     // [A]
    float* __restrict__ labels,         // [B,A,3]
    float* __restrict__ ofs,            // [B,A,21,2]
    int A, int B, int aligned4)
{
    __shared__ float  sA[CTILE*42];
    __shared__ float  s_base[NANCH*42];          // 12 x 21 x 2 base poses
    __shared__ float  s_shx[8], s_shy[8];        // per-pos shifts
    __shared__ float  sg[(BMAX*2+1)*42];         // + zero row at B*84
    __shared__ unsigned short sdw[BMAX*CTILE];
    __shared__ int s_allneg[BMAX];
    __shared__ int s_allout;
    __shared__ int s_in[CTILE];

    const int tid = threadIdx.x;
    const int a0  = blockIdx.x * CTILE;
    const int cnt = min(CTILE, A - a0);
    const int nfl = cnt * 42;
    const int nf4 = aligned4 ? (nfl >> 2) : 0;
    const int ng  = B * 84;
    const size_t bstride4 = ((size_t)A * 42) >> 2;

    int feat_w, feat_h;
    if (fwp) { feat_w = *fwp; feat_h = *fhp; }
    else {
        int pos = A / NANCH;
        feat_w = (int)rintf(sqrtf((float)pos));
        feat_h = pos / feat_w;
    }

    const int p0   = a0 / NANCH;
    const int npos = (a0 + cnt - 1) / NANCH - p0 + 1;   // <= 7

    if (tid < CTILE) s_in[tid] = 1;

    // ---- stage decision words (long-latency global loads, issued first) ----
    for (int i = tid; i < B*CTILE; i += CTHREADS) {
        int b = i >> 6, la = i & (CTILE-1);
        uint8_t d = (la < cnt) ? g_dec[(size_t)b*A + a0 + la] : (uint8_t)3;
        unsigned short r = (d == 2) ? (unsigned short)(b*84)
                         : (d == 1) ? (unsigned short)(b*84 + 42)
                         : (unsigned short)ng;
        sdw[i] = (unsigned short)(r | ((unsigned short)d << 12));
    }

    // ---- base pose table (float only) + shift pairs (tiny double work) ----
    {
        float cx, cy;
        ref_center(cx, cy);
        for (int i = tid; i < NANCH*42; i += CTHREADS) {
            int j = i / 42, e = i - j*42;
            s_base[i] = base_coord(j, e >> 1, e & 1, cx, cy);
        }
    }
    if (tid < npos) {
        int pos = p0 + tid;
        int ix  = pos % feat_w;
        int iy  = pos / feat_w;
        s_shx[tid] = (float)((double)ix * (256.0 / (double)feat_w));
        s_shy[tid] = (float)((double)iy * (256.0 / (double)feat_h));
    }
    __syncthreads();

    // ---- assemble anchor tile: base + shift (pure float adds) ----
    for (int i = tid; i < cnt*NKPT; i += CTHREADS) {
        int al = i / NKPT, k = i - al*NKPT;
        int a  = a0 + al;
        int j  = a % NANCH;
        int pl = a / NANCH - p0;
        float px = s_base[j*42 + 2*k]   + s_shx[pl];
        float py = s_base[j*42 + 2*k+1] + s_shy[pl];
        sA[al*42 + 2*k]   = px;
        sA[al*42 + 2*k+1] = py;
        if (!((px >= 0.f) && (py >= 0.f) && (px < 256.f) && (py < 256.f)))
            s_in[al] = 0;                        // benign race: all write 0
    }
    __syncthreads();

    // ---- flags ----
    if (tid < B) {
        int all0 = 1;
        #pragma unroll 8
        for (int la = 0; la < CTILE; la++)
            if ((sdw[tid*CTILE + la] >> 12) != 0) { all0 = 0; break; }
        s_allneg[tid] = all0;
    }
    if (tid == B) {
        int allo = 1;
        #pragma unroll 8
        for (int la = 0; la < CTILE; la++)
            if ((sdw[la] >> 12) != 3) { allo = 0; break; }
        s_allout = allo;
    }

    // ---- anchors + inside ----
    if (tid < cnt)
        __stcs(&inside_out[a0 + tid], s_in[tid] ? 1.f : 0.f);
    {
        float4* op = (float4*)(anchors_out + (size_t)a0*42);
        for (int f = tid; f < nf4; f += CTHREADS) __stcs(op + f, ((const float4*)sA)[f]);
        for (int o = (nf4 << 2) + tid; o < nfl; o += CTHREADS)
            anchors_out[(size_t)a0*42 + o] = sA[o];
    }
    __syncthreads();

    // ---- ALL-OUTSIDE fast path ----
    if (s_allout) {
        const float4 m1 = make_float4(-1.f, -1.f, -1.f, -1.f);
        const float4 z  = make_float4(0.f, 0.f, 0.f, 0.f);
        if (aligned4 && cnt == CTILE) {
            const int lf4 = (CTILE*3) >> 2;
            for (int b = 0; b < B; b++) {
                float4* lp = (float4*)(labels + ((size_t)b*A + a0)*3);
                for (int f = tid; f < lf4; f += CTHREADS) __stcs(lp + f, m1);
            }
        } else {
            for (int b = 0; b < B; b++)
                for (int o = tid; o < cnt*3; o += CTHREADS)
                    labels[((size_t)b*A + a0)*3 + o] = -1.f;
        }
        if (aligned4) {
            for (int b = 0; b < B; b++) {
                float4* op = (float4*)(ofs + ((size_t)b*A + a0)*42);
                for (int f = tid; f < nf4; f += CTHREADS) __stcs(op + f, z);
            }
        } else {
            for (int b = 0; b < B; b++)
                for (int o = tid; o < nfl; o += CTHREADS)
                    ofs[((size_t)b*A + a0)*42 + o] = 0.f;
        }
        return;
    }

    // ---- heavy path: stage gt xy (+zero row) ----
    for (int i = tid; i < ng + 42; i += CTHREADS) {
        float v = 0.f;
        if (i < ng) {
            int b2 = i / 42, e = i - b2*42;
            v = gt[b2*63 + 3*(e>>1) + (e&1)];
        }
        sg[i] = v;
    }
    __syncthreads();

    // ---- labels ----
    if (aligned4 && cnt == CTILE) {
        const int lf4 = (CTILE*3) >> 2;          // 48
        for (int idx = tid; idx < B*lf4; idx += CTHREADS) {
            int b = idx / lf4, f = idx - b*lf4;
            int o = f << 2;
            float4 v;
            float* vv = &v.x;
            int la = o / 3, c = o - la*3;
            #pragma unroll
            for (int i = 0; i < 4; i++) {
                int d = sdw[b*CTILE + la] >> 12;
                float val;
                if (d == 3) val = -1.f;
                else {
                    int want = (c == 0) ? 1 : (c == 2) ? 2 : 0;
                    val = (d == want) ? 1.f : 0.f;
                }
                vv[i] = val;
                if (++c == 3) { c = 0; ++la; }
            }
            __stcs((float4*)(labels + ((size_t)b*A + a0)*3) + f, v);
        }
    } else {
        for (int idx = tid; idx < B*cnt*3; idx += CTHREADS) {
            int b = idx / (cnt*3), o = idx - b*(cnt*3);
            int la = o / 3, c = o - la*3;
            int d = sdw[b*CTILE + la] >> 12;
            float val;
            if (d == 3) val = -1.f;
            else {
                int want = (c == 0) ? 1 : (c == 2) ? 2 : 0;
                val = (d == want) ? 1.f : 0.f;
            }
            labels[((size_t)b*A + a0)*3 + o] = val;
        }
    }

    // ---- offsets ----
    for (int f = tid; f < nf4; f += CTHREADS) {
        int o   = f << 2;
        int la0 = o / 42;
        int e0  = o - la0*42;
        int la3 = (o + 3) / 42;
        bool crossed = (la3 != la0);
        int e1 = e0 + 1, e2 = e0 + 2, e3 = e0 + 3;
        bool c1 = (e1 >= 42), c2 = (e2 >= 42), c3 = (e3 >= 42);
        if (c1) e1 -= 42;
        if (c2) e2 -= 42;
        if (c3) e3 -= 42;

        float4 av = ((const float4*)sA)[f];
        float4 vneg = make_float4(-av.x, -av.y, -av.z, -av.w);
        float4* op = (float4*)(ofs + (size_t)a0*42) + f;

        for (int b = 0; b < B; b++) {
            if (s_allneg[b]) {
                __stcs(op, vneg);
                op += bstride4;
                continue;
            }
            int base = b * CTILE;
            unsigned p0w = sdw[base + la0];
            unsigned p1w = crossed ? (unsigned)sdw[base + la3] : p0w;
            int   r0 = p0w & 0xFFF;
            int   r1 = p1w & 0xFFF;
            bool  z0 = (p0w >> 12) == 3;
            bool  z1 = (p1w >> 12) == 3;

            float4 v;
            v.x = z0 ? 0.f : (sg[r0 + e0] - av.x);
            v.y = (c1 ? z1 : z0) ? 0.f : (sg[(c1 ? r1 : r0) + e1] - av.y);
            v.z = (c2 ? z1 : z0) ? 0.f : (sg[(c2 ? r1 : r0) + e2] - av.z);
            v.w = (c3 ? z1 : z0) ? 0.f : (sg[(c3 ? r1 : r0) + e3] - av.w);
            __stcs(op, v);
            op += bstride4;
        }
    }
    for (int o = (nf4 << 2) + tid; o < nfl; o += CTHREADS) {
        int la = o / 42, e = o - la*42;
        float av = sA[o];
        for (int b = 0; b < B; b++) {
            unsigned p = sdw[b*CTILE + la];
            int r = p & 0xFFF;
            float v = ((p >> 12) == 3) ? 0.f : (sg[r + e] - av);
            ofs[((size_t)b*A + a0)*42 + o] = v;
        }
    }
}

extern "C" void kernel_launch(void* const* d_in, const int* in_sizes, int n_in,
                              void* d_out, int out_size)
{
    const float* gt = (const float*)d_in[0];
    const int*   ht = (const int*)d_in[1];
    const int*   fh = (n_in >= 4) ? (const int*)d_in[2] : nullptr;
    const int*   fw = (n_in >= 4) ? (const int*)d_in[3] : nullptr;
    float* out = (float*)d_out;

    int B = in_sizes[0] / (2*NKPT*3);
    if (B < 1) B = 1;
    if (B > BMAX) B = BMAX;
    long long denom = 42 + 1 + 3LL*B + 42LL*B;
    int A = (int)((long long)out_size / denom);

    dim3 gridA((A + 127) / 128, (B + BSPLIT - 1) / BSPLIT);
    phaseA_kernel<<<gridA, 128>>>(gt, ht, fh, fw, B, A);

    float* anchors_out = out;
    float* inside_out  = out + (size_t)A*42;
    float* labels      = out + (size_t)A*43;
    float* ofs         = labels + (size_t)3*B*A;
    int aligned4  = ((A & 3) == 0) ? 1 : 0;
    int blocksC = (A + CTILE - 1) / CTILE;
    phaseC_kernel<<<blocksC, CTHREADS>>>(gt, fh, fw, anchors_out, inside_out,
                                         labels, ofs, A, B, aligned4);
}

// round 13
// speedup vs baseline: 2.3755x; 2.3755x over previous
#include <cuda_runtime.h>
#include <stdint.h>
#include <math.h>

#define NKPT 21
#define NANCH 12
#define BMAX 32
#define CTILE 64
#define NTHR 512

__constant__ float c_ref[NKPT*2] = {
 213.33335876464844f, 124.50563049316406f,
 190.504638671875f,   115.11840057373047f,
 169.9791717529297f,  101.77180480957031f,
 146.72341918945312f,  96.25749206542969f,
 128.86770629882812f,  87.2344970703125f,
 150.34292602539062f, 101.61070251464844f,
 119.29926300048828f,  98.73982238769531f,
 100.03463745117188f,  99.74459838867188f,
  82.62400817871094f, 101.2509536743164f,
 148.91049194335938f, 112.71517181396484f,
 114.37303161621094f, 113.20121002197266f,
  91.90096282958984f, 116.49812316894531f,
  74.75020599365234f, 119.37875366210938f,
 149.59658813476562f, 124.09295654296875f,
 119.72419738769531f, 126.36898040771484f,
  99.59107208251953f, 129.40196228027344f,
  82.82524108886719f, 131.584228515625f,
 154.55911254882812f, 135.07681274414062f,
 133.8833770751953f,  140.85983276367188f,
 120.45906066894531f, 145.40306091308594f,
 106.21541595458984f, 150.072265625f
};

// (float)cos/sin of 0,90,180,270 deg (double-computed, cast)
__constant__ float c_trig[8] = {
 1.0f, 0.0f,
 6.123233995736766e-17f, 1.0f,
 -1.0f, 1.2246467991473532e-16f,
 -1.8369701987210297e-16f, -1.0f
};

__device__ __forceinline__ float ex2f(float x) {
    float y; asm("ex2.approx.f32 %0, %1;" : "=f"(y) : "f"(x)); return y;
}

__device__ __forceinline__ void ref_center(float& cx, float& cy) {
    float sx = 0.f, sy = 0.f;
    #pragma unroll
    for (int k = 0; k < NKPT; k++) { sx += c_ref[2*k]; sy += c_ref[2*k+1]; }
    cx = sx / 21.0f; cy = sy / 21.0f;
}

__device__ __forceinline__ float base_coord(int j, int k, int is_y,
                                            float cx, float cy) {
    int si = j >> 2, oi = j & 3;
    float sc  = (si == 0) ? 0.25f : ((si == 1) ? 0.5f : 1.0f);
    float cth = c_trig[2*oi], sth = c_trig[2*oi+1];
    float vx = c_ref[2*k]   - cx;
    float vy = c_ref[2*k+1] - cy;
    return is_y ? (cy + sc * (vx*sth + vy*cth))
                : (cx + sc * (vx*cth - vy*sth));
}

// -----------------------------------------------------------------------------
// Single fused kernel: per 64-anchor tile computes anchors (smem), inside,
// OKS decisions, labels, offsets. All-outside tiles (~75%) skip OKS entirely.
// -----------------------------------------------------------------------------
__global__ void __launch_bounds__(NTHR, 3) fused_kernel(
    const float* __restrict__ gt,   // [B,2,21,3]
    const int*   __restrict__ ht,   // [B,2]
    const int*   __restrict__ fhp,
    const int*   __restrict__ fwp,
    float* __restrict__ out,
    int B, int A, int aligned4)
{
    __shared__ float  sA[CTILE*42];
    __shared__ float  s_shx[8], s_shy[8];
    __shared__ float  sg[(BMAX*2+1)*42];         // raw gt xy + zero row at B*84
    __shared__ unsigned short sdw[BMAX*CTILE];
    __shared__ float    s_nc[BMAX*2];
    __shared__ float    s_nvinv[BMAX*2];
    __shared__ unsigned s_mask[BMAX*2];
    __shared__ int      s_ht[BMAX*2];
    __shared__ int      s_in[CTILE];
    __shared__ int      s_allneg[BMAX];
    __shared__ int      s_anyin;

    const int tid = threadIdx.x;
    const int a0  = blockIdx.x * CTILE;
    const int cnt = min(CTILE, A - a0);
    const int nfl = cnt * 42;
    const int nf4 = aligned4 ? (nfl >> 2) : 0;
    const int ng  = B * 84;
    const size_t bstride4 = ((size_t)A * 42) >> 2;

    float* anchors_out = out;
    float* inside_out  = out + (size_t)A*42;
    float* labels      = out + (size_t)A*43;
    float* ofs         = labels + (size_t)3*B*A;

    int feat_w, feat_h;
    if (fwp) { feat_w = *fwp; feat_h = *fhp; }
    else {
        int pos = A / NANCH;
        feat_w = (int)rintf(sqrtf((float)pos));
        feat_h = pos / feat_w;
    }

    const int p0   = a0 / NANCH;
    const int npos = (a0 + cnt - 1) / NANCH - p0 + 1;   // <= 7

    if (tid < CTILE) s_in[tid] = 1;
    if (tid == 0)    s_anyin = 0;

    // shifts (tiny double work, <=7 threads)
    if (tid < npos) {
        int pos = p0 + tid;
        int ix  = pos % feat_w;
        int iy  = pos / feat_w;
        s_shx[tid] = (float)((double)ix * (256.0 / (double)feat_w));
        s_shy[tid] = (float)((double)iy * (256.0 / (double)feat_h));
    }
    __syncthreads();

    // ---- assemble anchors into smem (pure float) ----
    {
        float cx, cy;
        ref_center(cx, cy);
        for (int i = tid; i < cnt*NKPT; i += NTHR) {
            int al = i / NKPT, k = i - al*NKPT;
            int a  = a0 + al;
            int j  = a % NANCH;
            int pl = a / NANCH - p0;
            float px = base_coord(j, k, 0, cx, cy) + s_shx[pl];
            float py = base_coord(j, k, 1, cx, cy) + s_shy[pl];
            sA[al*42 + 2*k]   = px;
            sA[al*42 + 2*k+1] = py;
            if (!((px >= 0.f) && (py >= 0.f) && (px < 256.f) && (py < 256.f)))
                s_in[al] = 0;                    // benign race
        }
    }
    __syncthreads();

    if (tid < CTILE && tid < cnt && s_in[tid]) s_anyin = 1;   // benign race

    // ---- anchors + inside stores (always) ----
    if (tid < cnt)
        __stcs(&inside_out[a0 + tid], s_in[tid] ? 1.f : 0.f);
    {
        float4* op = (float4*)(anchors_out + (size_t)a0*42);
        for (int f = tid; f < nf4; f += NTHR) __stcs(op + f, ((const float4*)sA)[f]);
        for (int o = (nf4 << 2) + tid; o < nfl; o += NTHR)
            anchors_out[(size_t)a0*42 + o] = sA[o];
    }
    __syncthreads();

    // ---- ALL-OUTSIDE fast path (~75% of tiles): pure fills ----
    if (!s_anyin) {
        const float4 m1 = make_float4(-1.f, -1.f, -1.f, -1.f);
        const float4 z  = make_float4(0.f, 0.f, 0.f, 0.f);
        if (aligned4 && cnt == CTILE) {
            const int lf4 = (CTILE*3) >> 2;
            for (int b = 0; b < B; b++) {
                float4* lp = (float4*)(labels + ((size_t)b*A + a0)*3);
                for (int f = tid; f < lf4; f += NTHR) __stcs(lp + f, m1);
            }
        } else {
            for (int b = 0; b < B; b++)
                for (int o = tid; o < cnt*3; o += NTHR)
                    labels[((size_t)b*A + a0)*3 + o] = -1.f;
        }
        if (aligned4) {
            for (int b = 0; b < B; b++) {
                float4* op = (float4*)(ofs + ((size_t)b*A + a0)*42);
                for (int f = tid; f < nf4; f += NTHR) __stcs(op + f, z);
            }
        } else {
            for (int b = 0; b < B; b++)
                for (int o = tid; o < nfl; o += NTHR)
                    ofs[((size_t)b*A + a0)*42 + o] = 0.f;
        }
        return;
    }

    // ---- heavy path: stage raw gt xy (+zero row) + coefficients ----
    for (int i = tid; i < ng + 42; i += NTHR) {
        float v = 0.f;
        if (i < ng) {
            int b2 = i / 42, e = i - b2*42;
            v = gt[b2*63 + 3*(e>>1) + (e&1)];
        }
        sg[i] = v;
    }
    if (tid < B*2) {
        const float* g = gt + (size_t)tid*63;
        float xmn = 3.4e38f, xmx = -3.4e38f, ymn = 3.4e38f, ymx = -3.4e38f, nv = 0.f;
        unsigned m = 0;
        #pragma unroll
        for (int k = 0; k < NKPT; k++) {
            float x = g[3*k], y = g[3*k+1];
            xmn = fminf(xmn, x); xmx = fmaxf(xmx, x);
            ymn = fminf(ymn, y); ymx = fmaxf(ymx, y);
            if (g[3*k+2] > 0.f) { nv += 1.f; m |= (1u << k); }
        }
        float s2 = fmaxf((xmx - xmn) * (ymx - ymn), 1.f);
        s_nc[tid]    = -1.442695040888963f / (2.f * s2 * 0.01f);
        s_nvinv[tid] = 1.f / fmaxf(nv, 1.f);
        s_mask[tid]  = m;
        s_ht[tid]    = ht[tid];
    }
    __syncthreads();

    // ---- OKS decisions: tasks (la, b), anchors read from smem ----
    {
        int la = tid & (CTILE-1);
        bool inside = (la < cnt) && (s_in[la] != 0);
        const float2* ap = (const float2*)(sA + la*42);
        for (int b = tid >> 6; b < B; b += NTHR/CTILE) {
            unsigned short w;
            if (!inside) {
                w = (unsigned short)(ng | (3u << 12));
            } else {
                const float2* g0 = (const float2*)(sg + b*84);
                const float2* g1 = g0 + NKPT;
                float nc0 = s_nc[2*b], nc1 = s_nc[2*b+1];
                unsigned m0 = s_mask[2*b], m1 = s_mask[2*b+1];
                float acc0 = 0.f, acc1 = 0.f;
                #pragma unroll
                for (int k = 0; k < NKPT; k++) {
                    float2 av = ap[k];
                    float2 p0 = g0[k];
                    float dx0 = av.x - p0.x, dy0 = av.y - p0.y;
                    float e0 = ex2f((dx0*dx0 + dy0*dy0) * nc0);
                    if (m0 & (1u << k)) acc0 += e0;
                    float2 p1 = g1[k];
                    float dx1 = av.x - p1.x, dy1 = av.y - p1.y;
                    float e1 = ex2f((dx1*dx1 + dy1*dy1) * nc1);
                    if (m1 & (1u << k)) acc1 += e1;
                }
                float sim0 = acc0 * s_nvinv[2*b];
                float sim1 = acc1 * s_nvinv[2*b+1];
                bool am0 = (sim0 >= sim1);
                float mxs = fmaxf(sim0, sim1);
                bool right = am0  && (mxs > 0.5f) && (s_ht[2*b]   == 1);
                bool left  = !am0 && (mxs > 0.5f) && (s_ht[2*b+1] == 1);
                int d = right ? 2 : (left ? 1 : 0);
                int r = (d == 2) ? (b*84) : (d == 1) ? (b*84 + 42) : ng;
                w = (unsigned short)(r | (d << 12));
            }
            sdw[b*CTILE + la] = w;
        }
    }
    __syncthreads();

    // ---- per-b allneg flags ----
    if (tid < B) {
        int all0 = 1;
        #pragma unroll 8
        for (int la = 0; la < CTILE; la++)
            if ((sdw[tid*CTILE + la] >> 12) != 0) { all0 = 0; break; }
        s_allneg[tid] = all0;
    }
    __syncthreads();

    // ---- labels ----
    if (aligned4 && cnt == CTILE) {
        const int lf4 = (CTILE*3) >> 2;          // 48
        for (int idx = tid; idx < B*lf4; idx += NTHR) {
            int b = idx / lf4, f = idx - b*lf4;
            int o = f << 2;
            float4 v;
            float* vv = &v.x;
            int la = o / 3, c = o - la*3;
            #pragma unroll
            for (int i = 0; i < 4; i++) {
                int d = sdw[b*CTILE + la] >> 12;
                float val;
                if (d == 3) val = -1.f;
                else {
                    int want = (c == 0) ? 1 : (c == 2) ? 2 : 0;
                    val = (d == want) ? 1.f : 0.f;
                }
                vv[i] = val;
                if (++c == 3) { c = 0; ++la; }
            }
            __stcs((float4*)(labels + ((size_t)b*A + a0)*3) + f, v);
        }
    } else {
        for (int idx = tid; idx < B*cnt*3; idx += NTHR) {
            int b = idx / (cnt*3), o = idx - b*(cnt*3);
            int la = o / 3, c = o - la*3;
            int d = sdw[b*CTILE + la] >> 12;
            float val;
            if (d == 3) val = -1.f;
            else {
                int want = (c == 0) ? 1 : (c == 2) ? 2 : 0;
                val = (d == want) ? 1.f : 0.f;
            }
            labels[((size_t)b*A + a0)*3 + o] = val;
        }
    }

    // ---- offsets ----
    for (int f = tid; f < nf4; f += NTHR) {
        int o   = f << 2;
        int la0 = o / 42;
        int e0  = o - la0*42;
        int la3 = (o + 3) / 42;
        bool crossed = (la3 != la0);
        int e1 = e0 + 1, e2 = e0 + 2, e3 = e0 + 3;
        bool c1 = (e1 >= 42), c2 = (e2 >= 42), c3 = (e3 >= 42);
        if (c1) e1 -= 42;
        if (c2) e2 -= 42;
        if (c3) e3 -= 42;

        float4 av = ((const float4*)sA)[f];
        float4 vneg = make_float4(-av.x, -av.y, -av.z, -av.w);
        float4* op = (float4*)(ofs + (size_t)a0*42) + f;

        for (int b = 0; b < B; b++) {
            if (s_allneg[b]) {
                __stcs(op, vneg);
                op += bstride4;
                continue;
            }
            int base = b * CTILE;
            unsigned p0w = sdw[base + la0];
            unsigned p1w = crossed ? (unsigned)sdw[base + la3] : p0w;
            int   r0 = p0w & 0xFFF;
            int   r1 = p1w & 0xFFF;
            bool  z0 = (p0w >> 12) == 3;
            bool  z1 = (p1w >> 12) == 3;

            float4 v;
            v.x = z0 ? 0.f : (sg[r0 + e0] - av.x);
            v.y = (c1 ? z1 : z0) ? 0.f : (sg[(c1 ? r1 : r0) + e1] - av.y);
            v.z = (c2 ? z1 : z0) ? 0.f : (sg[(c2 ? r1 : r0) + e2] - av.z);
            v.w = (c3 ? z1 : z0) ? 0.f : (sg[(c3 ? r1 : r0) + e3] - av.w);
            __stcs(op, v);
            op += bstride4;
        }
    }
    for (int o = (nf4 << 2) + tid; o < nfl; o += NTHR) {
        int la = o / 42, e = o - la*42;
        float av = sA[o];
        for (int b = 0; b < B; b++) {
            unsigned p = sdw[b*CTILE + la];
            int r = p & 0xFFF;
            float v = ((p >> 12) == 3) ? 0.f : (sg[r + e] - av);
            ofs[((size_t)b*A + a0)*42 + o] = v;
        }
    }
}

extern "C" void kernel_launch(void* const* d_in, const int* in_sizes, int n_in,
                              void* d_out, int out_size)
{
    const float* gt = (const float*)d_in[0];
    const int*   ht = (const int*)d_in[1];
    const int*   fh = (n_in >= 4) ? (const int*)d_in[2] : nullptr;
    const int*   fw = (n_in >= 4) ? (const int*)d_in[3] : nullptr;
    float* out = (float*)d_out;

    int B = in_sizes[0] / (2*NKPT*3);
    if (B < 1) B = 1;
    if (B > BMAX) B = BMAX;
    long long denom = 42 + 1 + 3LL*B + 42LL*B;
    int A = (int)((long long)out_size / denom);

    int aligned4 = ((A & 3) == 0) ? 1 : 0;
    int blocks = (A + CTILE - 1) / CTILE;
    fused_kernel<<<blocks, NTHR>>>(gt, ht, fh, fw, out, B, A, aligned4);
}

// round 14
// speedup vs baseline: 2.4521x; 1.0322x over previous
#include <cuda_runtime.h>
#include <stdint.h>
#include <math.h>

#define NKPT 21
#define NANCH 12
#define BMAX 32
#define CTILE 64
#define NTHR 512

__constant__ float c_ref[NKPT*2] = {
 213.33335876464844f, 124.50563049316406f,
 190.504638671875f,   115.11840057373047f,
 169.9791717529297f,  101.77180480957031f,
 146.72341918945312f,  96.25749206542969f,
 128.86770629882812f,  87.2344970703125f,
 150.34292602539062f, 101.61070251464844f,
 119.29926300048828f,  98.73982238769531f,
 100.03463745117188f,  99.74459838867188f,
  82.62400817871094f, 101.2509536743164f,
 148.91049194335938f, 112.71517181396484f,
 114.37303161621094f, 113.20121002197266f,
  91.90096282958984f, 116.49812316894531f,
  74.75020599365234f, 119.37875366210938f,
 149.59658813476562f, 124.09295654296875f,
 119.72419738769531f, 126.36898040771484f,
  99.59107208251953f, 129.40196228027344f,
  82.82524108886719f, 131.584228515625f,
 154.55911254882812f, 135.07681274414062f,
 133.8833770751953f,  140.85983276367188f,
 120.45906066894531f, 145.40306091308594f,
 106.21541595458984f, 150.072265625f
};

// (float)cos/sin of 0,90,180,270 deg (double-computed, cast)
__constant__ float c_trig[8] = {
 1.0f, 0.0f,
 6.123233995736766e-17f, 1.0f,
 -1.0f, 1.2246467991473532e-16f,
 -1.8369701987210297e-16f, -1.0f
};

__device__ __forceinline__ float ex2f(float x) {
    float y; asm("ex2.approx.f32 %0, %1;" : "=f"(y) : "f"(x)); return y;
}

__device__ __forceinline__ void ref_center(float& cx, float& cy) {
    float sx = 0.f, sy = 0.f;
    #pragma unroll
    for (int k = 0; k < NKPT; k++) { sx += c_ref[2*k]; sy += c_ref[2*k+1]; }
    cx = sx / 21.0f; cy = sy / 21.0f;
}

__device__ __forceinline__ float base_coord(int j, int k, int is_y,
                                            float cx, float cy) {
    int si = j >> 2, oi = j & 3;
    float sc  = (si == 0) ? 0.25f : ((si == 1) ? 0.5f : 1.0f);
    float cth = c_trig[2*oi], sth = c_trig[2*oi+1];
    float vx = c_ref[2*k]   - cx;
    float vy = c_ref[2*k+1] - cy;
    return is_y ? (cy + sc * (vx*sth + vy*cth))
                : (cx + sc * (vx*cth - vy*sth));
}

// -----------------------------------------------------------------------------
// Single fused kernel. After anchors are stored, outside anchors are zeroed in
// smem and d in {0,3} routes to the zero gt-row -> offsets loop is select-free.
// -----------------------------------------------------------------------------
__global__ void __launch_bounds__(NTHR, 3) fused_kernel(
    const float* __restrict__ gt,   // [B,2,21,3]
    const int*   __restrict__ ht,   // [B,2]
    const int*   __restrict__ fhp,
    const int*   __restrict__ fwp,
    float* __restrict__ out,
    int B, int A, int aligned4)
{
    __shared__ float  sA[CTILE*42];
    __shared__ float  s_shx[8], s_shy[8];
    __shared__ float  sg[(BMAX*2+1)*42];         // gt xy + zero row at B*84
    __shared__ unsigned short sdw[BMAX*CTILE];   // row(12b) | dec(2b @12)
    __shared__ float    s_nc[BMAX*2];
    __shared__ float    s_nvinv[BMAX*2];
    __shared__ unsigned s_mask[BMAX*2];
    __shared__ int      s_ht[BMAX*2];
    __shared__ int      s_in[CTILE];
    __shared__ int      s_allneg[BMAX];
    __shared__ int      s_anyin;

    const int tid = threadIdx.x;
    const int a0  = blockIdx.x * CTILE;
    const int cnt = min(CTILE, A - a0);
    const int nfl = cnt * 42;
    const int nf4 = aligned4 ? (nfl >> 2) : 0;
    const int ng  = B * 84;
    const size_t bstride4 = ((size_t)A * 42) >> 2;

    float* anchors_out = out;
    float* inside_out  = out + (size_t)A*42;
    float* labels      = out + (size_t)A*43;
    float* ofs         = labels + (size_t)3*B*A;

    int feat_w, feat_h;
    if (fwp) { feat_w = *fwp; feat_h = *fhp; }
    else {
        int pos = A / NANCH;
        feat_w = (int)rintf(sqrtf((float)pos));
        feat_h = pos / feat_w;
    }

    const int p0   = a0 / NANCH;
    const int npos = (a0 + cnt - 1) / NANCH - p0 + 1;   // <= 7

    if (tid < CTILE) s_in[tid] = 1;
    if (tid == 0)    s_anyin = 0;

    if (tid < npos) {
        int pos = p0 + tid;
        int ix  = pos % feat_w;
        int iy  = pos / feat_w;
        s_shx[tid] = (float)((double)ix * (256.0 / (double)feat_w));
        s_shy[tid] = (float)((double)iy * (256.0 / (double)feat_h));
    }
    __syncthreads();

    // ---- assemble anchors into smem (pure float) ----
    {
        float cx, cy;
        ref_center(cx, cy);
        for (int i = tid; i < cnt*NKPT; i += NTHR) {
            int al = i / NKPT, k = i - al*NKPT;
            int a  = a0 + al;
            int j  = a % NANCH;
            int pl = a / NANCH - p0;
            float px = base_coord(j, k, 0, cx, cy) + s_shx[pl];
            float py = base_coord(j, k, 1, cx, cy) + s_shy[pl];
            sA[al*42 + 2*k]   = px;
            sA[al*42 + 2*k+1] = py;
            if (!((px >= 0.f) && (py >= 0.f) && (px < 256.f) && (py < 256.f)))
                s_in[al] = 0;                    // benign race
        }
    }
    __syncthreads();

    if (tid < CTILE && tid < cnt && s_in[tid]) s_anyin = 1;   // benign race

    // ---- anchors + inside stores (always) ----
    if (tid < cnt)
        __stcs(&inside_out[a0 + tid], s_in[tid] ? 1.f : 0.f);
    {
        float4* op = (float4*)(anchors_out + (size_t)a0*42);
        for (int f = tid; f < nf4; f += NTHR) __stcs(op + f, ((const float4*)sA)[f]);
        for (int o = (nf4 << 2) + tid; o < nfl; o += NTHR)
            anchors_out[(size_t)a0*42 + o] = sA[o];
    }
    __syncthreads();

    // ---- ALL-OUTSIDE fast path (~75% of tiles): pure fills ----
    if (!s_anyin) {
        const float4 m1 = make_float4(-1.f, -1.f, -1.f, -1.f);
        const float4 z  = make_float4(0.f, 0.f, 0.f, 0.f);
        if (aligned4 && cnt == CTILE) {
            const int lf4 = (CTILE*3) >> 2;
            for (int b = 0; b < B; b++) {
                float4* lp = (float4*)(labels + ((size_t)b*A + a0)*3);
                for (int f = tid; f < lf4; f += NTHR) __stcs(lp + f, m1);
            }
        } else {
            for (int b = 0; b < B; b++)
                for (int o = tid; o < cnt*3; o += NTHR)
                    labels[((size_t)b*A + a0)*3 + o] = -1.f;
        }
        if (aligned4) {
            for (int b = 0; b < B; b++) {
                float4* op = (float4*)(ofs + ((size_t)b*A + a0)*42);
                for (int f = tid; f < nf4; f += NTHR) __stcs(op + f, z);
            }
        } else {
            for (int b = 0; b < B; b++)
                for (int o = tid; o < nfl; o += NTHR)
                    ofs[((size_t)b*A + a0)*42 + o] = 0.f;
        }
        return;
    }

    // ---- heavy path: zero outside anchors IN PLACE (global copy is done),
    //      stage gt xy (+zero row), coefficients ----
    for (int i = tid; i < nfl; i += NTHR) {
        int la = i / 42;
        if (!s_in[la]) sA[i] = 0.f;
    }
    for (int i = tid; i < ng + 42; i += NTHR) {
        float v = 0.f;
        if (i < ng) {
            int b2 = i / 42, e = i - b2*42;
            v = gt[b2*63 + 3*(e>>1) + (e&1)];
        }
        sg[i] = v;
    }
    if (tid < B*2) {
        const float* g = gt + (size_t)tid*63;
        float xmn = 3.4e38f, xmx = -3.4e38f, ymn = 3.4e38f, ymx = -3.4e38f, nv = 0.f;
        unsigned m = 0;
        #pragma unroll
        for (int k = 0; k < NKPT; k++) {
            float x = g[3*k], y = g[3*k+1];
            xmn = fminf(xmn, x); xmx = fmaxf(xmx, x);
            ymn = fminf(ymn, y); ymx = fmaxf(ymx, y);
            if (g[3*k+2] > 0.f) { nv += 1.f; m |= (1u << k); }
        }
        float s2 = fmaxf((xmx - xmn) * (ymx - ymn), 1.f);
        s_nc[tid]    = -1.442695040888963f / (2.f * s2 * 0.01f);
        s_nvinv[tid] = 1.f / fmaxf(nv, 1.f);
        s_mask[tid]  = m;
        s_ht[tid]    = ht[tid];
    }
    __syncthreads();

    // ---- OKS decisions: tasks (la, b); inside anchors only read sA ----
    {
        int la = tid & (CTILE-1);
        bool inside = (la < cnt) && (s_in[la] != 0);
        const float2* ap = (const float2*)(sA + la*42);
        for (int b = tid >> 6; b < B; b += NTHR/CTILE) {
            unsigned short w;
            if (!inside) {
                w = (unsigned short)(ng | (3u << 12));   // row=zero, dec=3
            } else {
                const float2* g0 = (const float2*)(sg + b*84);
                const float2* g1 = g0 + NKPT;
                float nc0 = s_nc[2*b], nc1 = s_nc[2*b+1];
                unsigned m0 = s_mask[2*b], m1 = s_mask[2*b+1];
                float acc0 = 0.f, acc1 = 0.f;
                #pragma unroll
                for (int k = 0; k < NKPT; k++) {
                    float2 av = ap[k];
                    float2 q0 = g0[k];
                    float dx0 = av.x - q0.x, dy0 = av.y - q0.y;
                    float e0 = ex2f((dx0*dx0 + dy0*dy0) * nc0);
                    if (m0 & (1u << k)) acc0 += e0;
                    float2 q1 = g1[k];
                    float dx1 = av.x - q1.x, dy1 = av.y - q1.y;
                    float e1 = ex2f((dx1*dx1 + dy1*dy1) * nc1);
                    if (m1 & (1u << k)) acc1 += e1;
                }
                float sim0 = acc0 * s_nvinv[2*b];
                float sim1 = acc1 * s_nvinv[2*b+1];
                bool am0 = (sim0 >= sim1);
                float mxs = fmaxf(sim0, sim1);
                bool right = am0  && (mxs > 0.5f) && (s_ht[2*b]   == 1);
                bool left  = !am0 && (mxs > 0.5f) && (s_ht[2*b+1] == 1);
                int d = right ? 2 : (left ? 1 : 0);
                int r = (d == 2) ? (b*84) : (d == 1) ? (b*84 + 42) : ng;  // neg -> zero row
                w = (unsigned short)(r | (d << 12));
            }
            sdw[b*CTILE + la] = w;
        }
    }
    __syncthreads();

    // ---- per-b allneg flags ----
    if (tid < B) {
        int all0 = 1;
        #pragma unroll 8
        for (int la = 0; la < CTILE; la++)
            if ((sdw[tid*CTILE + la] >> 12) != 0) { all0 = 0; break; }
        s_allneg[tid] = all0;
    }
    __syncthreads();

    // ---- labels ----
    if (aligned4 && cnt == CTILE) {
        const int lf4 = (CTILE*3) >> 2;          // 48
        for (int idx = tid; idx < B*lf4; idx += NTHR) {
            int b = idx / lf4, f = idx - b*lf4;
            int o = f << 2;
            float4 v;
            float* vv = &v.x;
            int la = o / 3, c = o - la*3;
            #pragma unroll
            for (int i = 0; i < 4; i++) {
                int d = sdw[b*CTILE + la] >> 12;
                float val;
                if (d == 3) val = -1.f;
                else {
                    int want = (c == 0) ? 1 : (c == 2) ? 2 : 0;
                    val = (d == want) ? 1.f : 0.f;
                }
                vv[i] = val;
                if (++c == 3) { c = 0; ++la; }
            }
            __stcs((float4*)(labels + ((size_t)b*A + a0)*3) + f, v);
        }
    } else {
        for (int idx = tid; idx < B*cnt*3; idx += NTHR) {
            int b = idx / (cnt*3), o = idx - b*(cnt*3);
            int la = o / 3, c = o - la*3;
            int d = sdw[b*CTILE + la] >> 12;
            float val;
            if (d == 3) val = -1.f;
            else {
                int want = (c == 0) ? 1 : (c == 2) ? 2 : 0;
                val = (d == want) ? 1.f : 0.f;
            }
            labels[((size_t)b*A + a0)*3 + o] = val;
        }
    }

    // ---- offsets: SELECT-FREE inner loop ----
    for (int f = tid; f < nf4; f += NTHR) {
        int o   = f << 2;
        int la0 = o / 42;
        int e0  = o - la0*42;
        int la3 = (o + 3) / 42;
        bool crossed = (la3 != la0);
        int e1 = e0 + 1, e2 = e0 + 2, e3 = e0 + 3;
        bool c1 = (e1 >= 42), c2 = (e2 >= 42), c3 = (e3 >= 42);
        if (c1) e1 -= 42;
        if (c2) e2 -= 42;
        if (c3) e3 -= 42;

        float4 av = ((const float4*)sA)[f];      // outside entries are zero
        float4 vneg = make_float4(-av.x, -av.y, -av.z, -av.w);
        float4* op = (float4*)(ofs + (size_t)a0*42) + f;

        for (int b = 0; b < B; b++) {
            if (s_allneg[b]) {
                __stcs(op, vneg);
                op += bstride4;
                continue;
            }
            int base = b * CTILE;
            int r0 = sdw[base + la0] & 0xFFF;
            int r1 = crossed ? (sdw[base + la3] & 0xFFF) : r0;

            float4 v;
            v.x = sg[r0 + e0]             - av.x;
            v.y = sg[(c1 ? r1 : r0) + e1] - av.y;
            v.z = sg[(c2 ? r1 : r0) + e2] - av.z;
            v.w = sg[(c3 ? r1 : r0) + e3] - av.w;
            __stcs(op, v);
            op += bstride4;
        }
    }
    for (int o = (nf4 << 2) + tid; o < nfl; o += NTHR) {
        int la = o / 42, e = o - la*42;
        float av = sA[o];
        for (int b = 0; b < B; b++) {
            int r = sdw[b*CTILE + la] & 0xFFF;
            ofs[((size_t)b*A + a0)*42 + o] = sg[r + e] - av;
        }
    }
}

extern "C" void kernel_launch(void* const* d_in, const int* in_sizes, int n_in,
                              void* d_out, int out_size)
{
    const float* gt = (const float*)d_in[0];
    const int*   ht = (const int*)d_in[1];
    const int*   fh = (n_in >= 4) ? (const int*)d_in[2] : nullptr;
    const int*   fw = (n_in >= 4) ? (const int*)d_in[3] : nullptr;
    float* out = (float*)d_out;

    int B = in_sizes[0] / (2*NKPT*3);
    if (B < 1) B = 1;
    if (B > BMAX) B = BMAX;
    long long denom = 42 + 1 + 3LL*B + 42LL*B;
    int A = (int)((long long)out_size / denom);

    int aligned4 = ((A & 3) == 0) ? 1 : 0;
    int blocks = (A + CTILE - 1) / CTILE;
    fused_kernel<<<blocks, NTHR>>>(gt, ht, fh, fw, out, B, A, aligned4);
}